// round 14
// baseline (speedup 1.0000x reference)
#include <cuda_runtime.h>
#include <cuda_bf16.h>
#include <cstdint>
#include <cstddef>

#define DI __device__ __forceinline__

// ---------------------------------------------------------------------------
// Problem constants
// ---------------------------------------------------------------------------
static constexpr int BATCH = 4;
static constexpr int DIM   = 4096;
static constexpr int KB    = 128;            // 4096/32 scale blocks per vector

// GEMM tiling (element == byte for e4m3)
static constexpr int BM = 128, BN = 256, BK = 128;   // BK in elements (=bytes)
static constexpr int NTHREADS = 512;          // 16 warps, 4x4
static constexpr int STAGES  = 3;
static constexpr int KTILES  = DIM / BK;      // 32
static constexpr int A_STAGE = BM * BK;       // 16384 B
static constexpr int B_STAGE = BN * BK;       // 32768 B
static constexpr int STAGE_B = A_STAGE + B_STAGE;            // 49152
static constexpr unsigned SMEM_TOTAL = STAGES * STAGE_B;     // 147456

// ---------------------------------------------------------------------------
// Scratch (device globals; no cudaMalloc allowed)
// ---------------------------------------------------------------------------
__device__ __align__(16) uint8_t g_Aq[(size_t)BATCH * DIM * DIM]; // [b][m][k] e4m3 (dequant value)
__device__ __align__(16) uint8_t g_Bq[(size_t)BATCH * DIM * DIM]; // [b][n][k] e4m3 (dequant value)

// ---------------------------------------------------------------------------
// Helpers
// ---------------------------------------------------------------------------
DI uint32_t smem_u32(const void* p) {
    uint32_t a;
    asm("{ .reg .u64 t; cvta.to.shared.u64 t, %1; cvt.u32.u64 %0, t; }" : "=r"(a) : "l"(p));
    return a;
}

DI void cp_async16(uint32_t dst, const void* src) {
    asm volatile("cp.async.cg.shared.global [%0], [%1], 16;" :: "r"(dst), "l"(src) : "memory");
}
DI void cp_commit() { asm volatile("cp.async.commit_group;" ::: "memory"); }
template <int N> DI void cp_wait() { asm volatile("cp.async.wait_group %0;" :: "n"(N) : "memory"); }

DI void ldmatrix_x4(uint32_t& r0, uint32_t& r1, uint32_t& r2, uint32_t& r3, uint32_t addr) {
    asm volatile("ldmatrix.sync.aligned.m8n8.x4.shared.b16 {%0,%1,%2,%3}, [%4];"
                 : "=r"(r0), "=r"(r1), "=r"(r2), "=r"(r3) : "r"(addr));
}

// FP8 e4m3 MMA, fp32 accumulate. Byte-level fragment layout identical to
// m16n8k16.bf16 (a2/b1 live at +16 bytes along k; 4-byte lane groups).
DI void mma_fp8(float& c0, float& c1, float& c2, float& c3,
                uint32_t a0, uint32_t a1, uint32_t a2, uint32_t a3,
                uint32_t b0, uint32_t b1) {
    asm volatile(
        "mma.sync.aligned.m16n8k32.row.col.f32.e4m3.e4m3.f32 "
        "{%0,%1,%2,%3}, {%4,%5,%6,%7}, {%8,%9}, {%0,%1,%2,%3};"
        : "+f"(c0), "+f"(c1), "+f"(c2), "+f"(c3)
        : "r"(a0), "r"(a1), "r"(a2), "r"(a3), "r"(b0), "r"(b1));
}

DI uint32_t swz(uint32_t off) { return off ^ ((off >> 3) & 0x70); }   // SW128, 128B rows

// ---------------------------------------------------------------------------
// MX fake-quantization -> e4m3 byte holding the exact dequantized value
// q * 2^(shexp-2), q in {0,.5,1,1.5,2,3,4,6}: mantissa <=1 bit -> e4m3-exact.
// ---------------------------------------------------------------------------
DI uint32_t quant_e4m3_val(float x, float inv, float scale) {
    float v = x * inv;                        // exact (power-of-2 inv)
    float a = fminf(fabsf(v), 6.0f);
    float q;
    if (a < 2.0f)      q = rintf(a * 2.0f) * 0.5f;   // step .5, RNE (== jnp.round)
    else if (a < 4.0f) q = rintf(a);                 // step 1
    else               q = rintf(a * 0.5f) * 2.0f;   // step 2
    float f = q * scale;                      // exact; e4m3-normal for all real data
    uint32_t b = 0;
    if (f != 0.0f)
        b = ((__float_as_uint(f) >> 20) - 960u) & 0x7Fu;   // fp32 -> e4m3 bits (exact)
    if (v < 0.0f) b |= 0x80u;
    return b;
}

DI void quant_block32(const float* x, uint32_t* w /*8 packed words*/) {
    float amax = 0.0f;
#pragma unroll
    for (int i = 0; i < 32; ++i) amax = fmaxf(amax, fabsf(x[i]));
    float inv, scale;
    if (amax > 0.0f) {
        int eb = (int)(__float_as_uint(amax) >> 23) & 0xFF;  // floor(log2)+127
        int sb = eb - 2;
        if (sb < 1) sb = 1;
        scale = __uint_as_float((uint32_t)sb << 23);          // exact 2^(shexp-2)
        inv   = __uint_as_float((uint32_t)(254 - sb) << 23);  // exact reciprocal
    } else {
        scale = 1.0f; inv = 1.0f;
    }
#pragma unroll
    for (int i = 0; i < 8; ++i) {
        uint32_t b0 = quant_e4m3_val(x[i*4+0], inv, scale);
        uint32_t b1 = quant_e4m3_val(x[i*4+1], inv, scale);
        uint32_t b2 = quant_e4m3_val(x[i*4+2], inv, scale);
        uint32_t b3 = quant_e4m3_val(x[i*4+3], inv, scale);
        w[i] = b0 | (b1 << 8) | (b2 << 16) | (b3 << 24);
    }
}

// A: [b][m][k] fp32, quantize along k (contiguous). One thread per 32-block.
__global__ void __launch_bounds__(256) quantA_kernel(const float* __restrict__ A) {
    size_t idx = (size_t)blockIdx.x * 256 + threadIdx.x;
    const float4* src = (const float4*)(A + idx * 32);
    float x[32];
#pragma unroll
    for (int i = 0; i < 8; ++i) {
        float4 v = src[i];
        x[i*4+0] = v.x; x[i*4+1] = v.y; x[i*4+2] = v.z; x[i*4+3] = v.w;
    }
    uint32_t w[8];
    quant_block32(x, w);
    uint4* dst = (uint4*)(g_Aq + idx * 32);
    dst[0] = make_uint4(w[0], w[1], w[2], w[3]);
    dst[1] = make_uint4(w[4], w[5], w[6], w[7]);
}

// B: [b][k][n] fp32, quantize along k (stride DIM). Output transposed: [b][n][k].
__global__ void __launch_bounds__(256) quantB_kernel(const float* __restrict__ B) {
    int n  = blockIdx.x * 256 + threadIdx.x;
    int kb = blockIdx.y;
    int b  = blockIdx.z;
    const float* src = B + ((size_t)b << 24) + (size_t)kb * 32 * DIM + n;
    float x[32];
#pragma unroll
    for (int r = 0; r < 32; ++r) x[r] = src[(size_t)r * DIM];
    uint32_t w[8];
    quant_block32(x, w);
    uint4* dst = (uint4*)(g_Bq + ((size_t)b << 24) + (size_t)n * DIM + kb * 32);
    dst[0] = make_uint4(w[0], w[1], w[2], w[3]);
    dst[1] = make_uint4(w[4], w[5], w[6], w[7]);
}

// ---------------------------------------------------------------------------
// GEMM: 128x256 CTA tile, e4m3 mma.sync m16n8k32, 3-stage cp.async pipeline
// 16 warps in 4x4 grid; warp tile 32(M) x 64(N); BK = 128 bytes per stage row.
// ---------------------------------------------------------------------------
DI void load_stage(uint32_t sb_, int stage, const uint8_t* Ab,
                   const uint8_t* Bb, int kt, int tid) {
    uint32_t sA = sb_ + stage * STAGE_B;
    uint32_t sB = sA + A_STAGE;
    const uint8_t* Ag = Ab + (size_t)kt * BK;
    const uint8_t* Bg = Bb + (size_t)kt * BK;
    // A: 128 rows x 128B = 1024 16B-chunks
#pragma unroll
    for (int t = 0; t < 2; ++t) {
        int c   = tid + t * NTHREADS;
        int row = c >> 3;
        int cc  = (c & 7) * 16;
        cp_async16(sA + swz((uint32_t)(row * 128 + cc)),
                   Ag + (size_t)row * DIM + cc);
    }
    // B: 256 rows x 128B = 2048 16B-chunks
#pragma unroll
    for (int t = 0; t < 4; ++t) {
        int c   = tid + t * NTHREADS;
        int row = c >> 3;
        int cc  = (c & 7) * 16;
        cp_async16(sB + swz((uint32_t)(row * 128 + cc)),
                   Bg + (size_t)row * DIM + cc);
    }
}

__global__ void __launch_bounds__(NTHREADS, 1)
gemm_kernel(float* __restrict__ out) {
    extern __shared__ char smem[];
    uint32_t sb_ = smem_u32(smem);
    int tid = threadIdx.x, warp = tid >> 5, lane = tid & 31;
    int wm = warp >> 2, wn = warp & 3;        // 4x4 warp grid
    int tn = blockIdx.x, tm = blockIdx.y, b = blockIdx.z;

    const uint8_t* Abase = g_Aq + ((size_t)b << 24) + (size_t)tm * BM * DIM;
    const uint8_t* Bbase = g_Bq + ((size_t)b << 24) + (size_t)tn * BN * DIM;

    float c[2][8][4];
#pragma unroll
    for (int i = 0; i < 2; ++i)
#pragma unroll
        for (int j = 0; j < 8; ++j)
#pragma unroll
            for (int q = 0; q < 4; ++q) c[i][j][q] = 0.0f;

    // prologue: prefetch STAGES-1 stages
#pragma unroll
    for (int p = 0; p < STAGES - 1; ++p) {
        load_stage(sb_, p, Abase, Bbase, p, tid);
        cp_commit();
    }

    // Pre-swizzled ldmatrix base addresses (ks=0). k-step advance is XOR:
    // base col-byte is 0/16 (bit 4), kx in {0,32,64,96} (bits 5-6), and the
    // swizzle XOR term depends only on row bits -> swz(base+kx)=swz(base)^kx.
    uint32_t a_base[2], b_base[4];
#pragma unroll
    for (int mt = 0; mt < 2; ++mt) {
        int r = wm * 32 + mt * 16 + (lane & 15);
        int cbyte = (lane >> 4) * 16;
        a_base[mt] = swz((uint32_t)(r * 128 + cbyte));
    }
#pragma unroll
    for (int p = 0; p < 4; ++p) {
        int m = lane >> 3;
        int r = wn * 64 + p * 16 + ((m >> 1) * 8) + (lane & 7);
        int cbyte = (m & 1) * 16;
        b_base[p] = swz((uint32_t)(r * 128 + cbyte));
    }

    for (int i = 0; i < KTILES; ++i) {
        cp_wait<STAGES - 2>();
        __syncthreads();          // single barrier per iteration

        int pf = i + STAGES - 1;
        if (pf < KTILES) {
            load_stage(sb_, pf % STAGES, Abase, Bbase, pf, tid);
        }
        cp_commit();              // uniform group count even when empty

        uint32_t stA = sb_ + (i % STAGES) * STAGE_B;
        uint32_t stB = stA + A_STAGE;
#pragma unroll
        for (int ks = 0; ks < 4; ++ks) {       // 4 x k32 = BK 128
            uint32_t kx = (uint32_t)(ks * 32);
            uint32_t af[2][4];
#pragma unroll
            for (int mt = 0; mt < 2; ++mt)
                ldmatrix_x4(af[mt][0], af[mt][1], af[mt][2], af[mt][3],
                            stA + (a_base[mt] ^ kx));
            uint32_t bf[8][2];
#pragma unroll
            for (int p = 0; p < 4; ++p) {
                uint32_t r0, r1, r2, r3;
                ldmatrix_x4(r0, r1, r2, r3, stB + (b_base[p] ^ kx));
                bf[p*2+0][0] = r0; bf[p*2+0][1] = r1;
                bf[p*2+1][0] = r2; bf[p*2+1][1] = r3;
            }
#pragma unroll
            for (int mt = 0; mt < 2; ++mt)
#pragma unroll
                for (int nt = 0; nt < 8; ++nt)
                    mma_fp8(c[mt][nt][0], c[mt][nt][1], c[mt][nt][2], c[mt][nt][3],
                            af[mt][0], af[mt][1], af[mt][2], af[mt][3],
                            bf[nt][0], bf[nt][1]);
        }
    }

    // epilogue: direct global stores (float2 per reg pair)
    int g = lane >> 2, t4 = lane & 3;
    float* obase = out + ((size_t)b << 24)
                 + (size_t)(tm * BM + wm * 32) * DIM + tn * BN + wn * 64;
#pragma unroll
    for (int mt = 0; mt < 2; ++mt) {
#pragma unroll
        for (int nt = 0; nt < 8; ++nt) {
            int colb = nt * 8 + t4 * 2;
            float* p0 = obase + (size_t)(mt * 16 + g) * DIM + colb;
            *(float2*)p0 = make_float2(c[mt][nt][0], c[mt][nt][1]);
            float* p1 = obase + (size_t)(mt * 16 + g + 8) * DIM + colb;
            *(float2*)p1 = make_float2(c[mt][nt][2], c[mt][nt][3]);
        }
    }
}

// ---------------------------------------------------------------------------
extern "C" void kernel_launch(void* const* d_in, const int* in_sizes, int n_in,
                              void* d_out, int out_size) {
    const float* A = (const float*)d_in[0];
    const float* B = (const float*)d_in[1];
    float* out = (float*)d_out;

    quantA_kernel<<<(BATCH * DIM * KB) / 256, 256>>>(A);
    quantB_kernel<<<dim3(DIM / 256, KB, BATCH), 256>>>(B);

    cudaFuncSetAttribute(gemm_kernel, cudaFuncAttributeMaxDynamicSharedMemorySize, SMEM_TOTAL);
    gemm_kernel<<<dim3(DIM / BN, DIM / BM, BATCH), NTHREADS, SMEM_TOTAL>>>(out);
}

// round 15
// speedup vs baseline: 1.0002x; 1.0002x over previous
#include <cuda_runtime.h>
#include <cuda_bf16.h>
#include <cstdint>
#include <cstddef>

#define DI __device__ __forceinline__

// ---------------------------------------------------------------------------
// Problem constants
// ---------------------------------------------------------------------------
static constexpr int BATCH = 4;
static constexpr int DIM   = 4096;
static constexpr int KB    = 128;            // 4096/32 scale blocks per vector

// GEMM tiling (element == byte for e4m3)
static constexpr int BM = 128, BN = 256, BK = 128;   // BK in elements (=bytes)
static constexpr int NTHREADS = 512;          // 16 warps, 4x4
static constexpr int STAGES  = 3;
static constexpr int KTILES  = DIM / BK;      // 32
static constexpr int A_STAGE = BM * BK;       // 16384 B
static constexpr int B_STAGE = BN * BK;       // 32768 B
static constexpr int STAGE_B = A_STAGE + B_STAGE;            // 49152
static constexpr unsigned SMEM_TOTAL = STAGES * STAGE_B;     // 147456

// ---------------------------------------------------------------------------
// Scratch (device globals; no cudaMalloc allowed)
// ---------------------------------------------------------------------------
__device__ __align__(16) uint8_t g_Aq[(size_t)BATCH * DIM * DIM]; // [b][m][k] e4m3 (dequant value)
__device__ __align__(16) uint8_t g_Bq[(size_t)BATCH * DIM * DIM]; // [b][n][k] e4m3 (dequant value)

// ---------------------------------------------------------------------------
// Helpers
// ---------------------------------------------------------------------------
DI uint32_t smem_u32(const void* p) {
    uint32_t a;
    asm("{ .reg .u64 t; cvta.to.shared.u64 t, %1; cvt.u32.u64 %0, t; }" : "=r"(a) : "l"(p));
    return a;
}

DI void cp_async16(uint32_t dst, const void* src) {
    asm volatile("cp.async.cg.shared.global [%0], [%1], 16;" :: "r"(dst), "l"(src) : "memory");
}
DI void cp_commit() { asm volatile("cp.async.commit_group;" ::: "memory"); }
template <int N> DI void cp_wait() { asm volatile("cp.async.wait_group %0;" :: "n"(N) : "memory"); }

DI void ldmatrix_x4(uint32_t& r0, uint32_t& r1, uint32_t& r2, uint32_t& r3, uint32_t addr) {
    asm volatile("ldmatrix.sync.aligned.m8n8.x4.shared.b16 {%0,%1,%2,%3}, [%4];"
                 : "=r"(r0), "=r"(r1), "=r"(r2), "=r"(r3) : "r"(addr));
}

// FP8 e4m3 MMA, fp32 accumulate. Byte-level fragment layout identical to
// m16n8k16.bf16 (a2/b1 live at +16 bytes along k; 4-byte lane groups).
DI void mma_fp8(float& c0, float& c1, float& c2, float& c3,
                uint32_t a0, uint32_t a1, uint32_t a2, uint32_t a3,
                uint32_t b0, uint32_t b1) {
    asm volatile(
        "mma.sync.aligned.m16n8k32.row.col.f32.e4m3.e4m3.f32 "
        "{%0,%1,%2,%3}, {%4,%5,%6,%7}, {%8,%9}, {%0,%1,%2,%3};"
        : "+f"(c0), "+f"(c1), "+f"(c2), "+f"(c3)
        : "r"(a0), "r"(a1), "r"(a2), "r"(a3), "r"(b0), "r"(b1));
}

DI uint32_t swz(uint32_t off) { return off ^ ((off >> 3) & 0x70); }   // SW128, 128B rows

// ---------------------------------------------------------------------------
// MX fake-quantization -> e4m3 byte holding the exact dequantized value
// q * 2^(shexp-2), q in {0,.5,1,1.5,2,3,4,6}: mantissa <=1 bit -> e4m3-exact.
// ---------------------------------------------------------------------------
DI uint32_t quant_e4m3_val(float x, float inv, float scale) {
    float v = x * inv;                        // exact (power-of-2 inv)
    float a = fminf(fabsf(v), 6.0f);
    float q;
    if (a < 2.0f)      q = rintf(a * 2.0f) * 0.5f;   // step .5, RNE (== jnp.round)
    else if (a < 4.0f) q = rintf(a);                 // step 1
    else               q = rintf(a * 0.5f) * 2.0f;   // step 2
    float f = q * scale;                      // exact; e4m3-normal for all real data
    uint32_t b = 0;
    if (f != 0.0f)
        b = ((__float_as_uint(f) >> 20) - 960u) & 0x7Fu;   // fp32 -> e4m3 bits (exact)
    if (v < 0.0f) b |= 0x80u;
    return b;
}

DI void quant_block32(const float* x, uint32_t* w /*8 packed words*/) {
    float amax = 0.0f;
#pragma unroll
    for (int i = 0; i < 32; ++i) amax = fmaxf(amax, fabsf(x[i]));
    float inv, scale;
    if (amax > 0.0f) {
        int eb = (int)(__float_as_uint(amax) >> 23) & 0xFF;  // floor(log2)+127
        int sb = eb - 2;
        if (sb < 1) sb = 1;
        scale = __uint_as_float((uint32_t)sb << 23);          // exact 2^(shexp-2)
        inv   = __uint_as_float((uint32_t)(254 - sb) << 23);  // exact reciprocal
    } else {
        scale = 1.0f; inv = 1.0f;
    }
#pragma unroll
    for (int i = 0; i < 8; ++i) {
        uint32_t b0 = quant_e4m3_val(x[i*4+0], inv, scale);
        uint32_t b1 = quant_e4m3_val(x[i*4+1], inv, scale);
        uint32_t b2 = quant_e4m3_val(x[i*4+2], inv, scale);
        uint32_t b3 = quant_e4m3_val(x[i*4+3], inv, scale);
        w[i] = b0 | (b1 << 8) | (b2 << 16) | (b3 << 24);
    }
}

// A: [b][m][k] fp32, quantize along k (contiguous). One thread per 32-block.
__global__ void __launch_bounds__(256) quantA_kernel(const float* __restrict__ A) {
    size_t idx = (size_t)blockIdx.x * 256 + threadIdx.x;
    const float4* src = (const float4*)(A + idx * 32);
    float x[32];
#pragma unroll
    for (int i = 0; i < 8; ++i) {
        float4 v = src[i];
        x[i*4+0] = v.x; x[i*4+1] = v.y; x[i*4+2] = v.z; x[i*4+3] = v.w;
    }
    uint32_t w[8];
    quant_block32(x, w);
    uint4* dst = (uint4*)(g_Aq + idx * 32);
    dst[0] = make_uint4(w[0], w[1], w[2], w[3]);
    dst[1] = make_uint4(w[4], w[5], w[6], w[7]);
}

// B: [b][k][n] fp32, quantize along k (stride DIM). Output transposed: [b][n][k].
__global__ void __launch_bounds__(256) quantB_kernel(const float* __restrict__ B) {
    int n  = blockIdx.x * 256 + threadIdx.x;
    int kb = blockIdx.y;
    int b  = blockIdx.z;
    const float* src = B + ((size_t)b << 24) + (size_t)kb * 32 * DIM + n;
    float x[32];
#pragma unroll
    for (int r = 0; r < 32; ++r) x[r] = src[(size_t)r * DIM];
    uint32_t w[8];
    quant_block32(x, w);
    uint4* dst = (uint4*)(g_Bq + ((size_t)b << 24) + (size_t)n * DIM + kb * 32);
    dst[0] = make_uint4(w[0], w[1], w[2], w[3]);
    dst[1] = make_uint4(w[4], w[5], w[6], w[7]);
}

// ---------------------------------------------------------------------------
// GEMM: 128x256 CTA tile, e4m3 mma.sync m16n8k32, 3-stage cp.async pipeline
// 16 warps in 4x4 grid; warp tile 32(M) x 64(N); BK = 128 bytes per stage row.
// ---------------------------------------------------------------------------
DI void load_stage(uint32_t sb_, int stage, const uint8_t* Ab,
                   const uint8_t* Bb, int kt, int tid) {
    uint32_t sA = sb_ + stage * STAGE_B;
    uint32_t sB = sA + A_STAGE;
    const uint8_t* Ag = Ab + (size_t)kt * BK;
    const uint8_t* Bg = Bb + (size_t)kt * BK;
    // A: 128 rows x 128B = 1024 16B-chunks
#pragma unroll
    for (int t = 0; t < 2; ++t) {
        int c   = tid + t * NTHREADS;
        int row = c >> 3;
        int cc  = (c & 7) * 16;
        cp_async16(sA + swz((uint32_t)(row * 128 + cc)),
                   Ag + (size_t)row * DIM + cc);
    }
    // B: 256 rows x 128B = 2048 16B-chunks
#pragma unroll
    for (int t = 0; t < 4; ++t) {
        int c   = tid + t * NTHREADS;
        int row = c >> 3;
        int cc  = (c & 7) * 16;
        cp_async16(sB + swz((uint32_t)(row * 128 + cc)),
                   Bg + (size_t)row * DIM + cc);
    }
}

__global__ void __launch_bounds__(NTHREADS, 1)
gemm_kernel(float* __restrict__ out) {
    extern __shared__ char smem[];
    uint32_t sb_ = smem_u32(smem);
    int tid = threadIdx.x, warp = tid >> 5, lane = tid & 31;
    int wm = warp >> 2, wn = warp & 3;        // 4x4 warp grid
    int tn = blockIdx.x, tm = blockIdx.y, b = blockIdx.z;

    const uint8_t* Abase = g_Aq + ((size_t)b << 24) + (size_t)tm * BM * DIM;
    const uint8_t* Bbase = g_Bq + ((size_t)b << 24) + (size_t)tn * BN * DIM;

    float c[2][8][4];
#pragma unroll
    for (int i = 0; i < 2; ++i)
#pragma unroll
        for (int j = 0; j < 8; ++j)
#pragma unroll
            for (int q = 0; q < 4; ++q) c[i][j][q] = 0.0f;

    // prologue: prefetch STAGES-1 stages
#pragma unroll
    for (int p = 0; p < STAGES - 1; ++p) {
        load_stage(sb_, p, Abase, Bbase, p, tid);
        cp_commit();
    }

    // Pre-swizzled ldmatrix base addresses (ks=0). k-step advance is XOR:
    // base col-byte is 0/16 (bit 4), kx in {0,32,64,96} (bits 5-6), and the
    // swizzle XOR term depends only on row bits -> swz(base+kx)=swz(base)^kx.
    uint32_t a_base[2], b_base[4];
#pragma unroll
    for (int mt = 0; mt < 2; ++mt) {
        int r = wm * 32 + mt * 16 + (lane & 15);
        int cbyte = (lane >> 4) * 16;
        a_base[mt] = swz((uint32_t)(r * 128 + cbyte));
    }
#pragma unroll
    for (int p = 0; p < 4; ++p) {
        int m = lane >> 3;
        int r = wn * 64 + p * 16 + ((m >> 1) * 8) + (lane & 7);
        int cbyte = (m & 1) * 16;
        b_base[p] = swz((uint32_t)(r * 128 + cbyte));
    }

    for (int i = 0; i < KTILES; ++i) {
        cp_wait<STAGES - 2>();
        __syncthreads();          // single barrier per iteration

        int pf = i + STAGES - 1;
        if (pf < KTILES) {
            load_stage(sb_, pf % STAGES, Abase, Bbase, pf, tid);
        }
        cp_commit();              // uniform group count even when empty

        uint32_t stA = sb_ + (i % STAGES) * STAGE_B;
        uint32_t stB = stA + A_STAGE;
#pragma unroll
        for (int ks = 0; ks < 4; ++ks) {       // 4 x k32 = BK 128
            uint32_t kx = (uint32_t)(ks * 32);
            uint32_t af[2][4];
#pragma unroll
            for (int mt = 0; mt < 2; ++mt)
                ldmatrix_x4(af[mt][0], af[mt][1], af[mt][2], af[mt][3],
                            stA + (a_base[mt] ^ kx));
            uint32_t bf[8][2];
#pragma unroll
            for (int p = 0; p < 4; ++p) {
                uint32_t r0, r1, r2, r3;
                ldmatrix_x4(r0, r1, r2, r3, stB + (b_base[p] ^ kx));
                bf[p*2+0][0] = r0; bf[p*2+0][1] = r1;
                bf[p*2+1][0] = r2; bf[p*2+1][1] = r3;
            }
#pragma unroll
            for (int mt = 0; mt < 2; ++mt)
#pragma unroll
                for (int nt = 0; nt < 8; ++nt)
                    mma_fp8(c[mt][nt][0], c[mt][nt][1], c[mt][nt][2], c[mt][nt][3],
                            af[mt][0], af[mt][1], af[mt][2], af[mt][3],
                            bf[nt][0], bf[nt][1]);
        }
    }

    // epilogue: direct global stores (float2 per reg pair)
    int g = lane >> 2, t4 = lane & 3;
    float* obase = out + ((size_t)b << 24)
                 + (size_t)(tm * BM + wm * 32) * DIM + tn * BN + wn * 64;
#pragma unroll
    for (int mt = 0; mt < 2; ++mt) {
#pragma unroll
        for (int nt = 0; nt < 8; ++nt) {
            int colb = nt * 8 + t4 * 2;
            float* p0 = obase + (size_t)(mt * 16 + g) * DIM + colb;
            *(float2*)p0 = make_float2(c[mt][nt][0], c[mt][nt][1]);
            float* p1 = obase + (size_t)(mt * 16 + g + 8) * DIM + colb;
            *(float2*)p1 = make_float2(c[mt][nt][2], c[mt][nt][3]);
        }
    }
}

// ---------------------------------------------------------------------------
extern "C" void kernel_launch(void* const* d_in, const int* in_sizes, int n_in,
                              void* d_out, int out_size) {
    const float* A = (const float*)d_in[0];
    const float* B = (const float*)d_in[1];
    float* out = (float*)d_out;

    quantA_kernel<<<(BATCH * DIM * KB) / 256, 256>>>(A);
    quantB_kernel<<<dim3(DIM / 256, KB, BATCH), 256>>>(B);

    cudaFuncSetAttribute(gemm_kernel, cudaFuncAttributeMaxDynamicSharedMemorySize, SMEM_TOTAL);
    gemm_kernel<<<dim3(DIM / BN, DIM / BM, BATCH), NTHREADS, SMEM_TOTAL>>>(out);
}

// round 16
// speedup vs baseline: 1.0005x; 1.0004x over previous
#include <cuda_runtime.h>
#include <cuda_bf16.h>
#include <cstdint>
#include <cstddef>

#define DI __device__ __forceinline__

// ---------------------------------------------------------------------------
// Problem constants
// ---------------------------------------------------------------------------
static constexpr int BATCH = 4;
static constexpr int DIM   = 4096;
static constexpr int KB    = 128;            // 4096/32 scale blocks per vector

// GEMM tiling (element == byte for e4m3)
static constexpr int BM = 128, BN = 256, BK = 128;   // BK in elements (=bytes)
static constexpr int NTHREADS = 512;          // 16 warps, 4x4
static constexpr int STAGES  = 3;
static constexpr int KTILES  = DIM / BK;      // 32
static constexpr int A_STAGE = BM * BK;       // 16384 B
static constexpr int B_STAGE = BN * BK;       // 32768 B
static constexpr int STAGE_B = A_STAGE + B_STAGE;            // 49152
static constexpr unsigned SMEM_TOTAL = STAGES * STAGE_B;     // 147456

// ---------------------------------------------------------------------------
// Scratch (device globals; no cudaMalloc allowed)
// ---------------------------------------------------------------------------
__device__ __align__(16) uint8_t g_Aq[(size_t)BATCH * DIM * DIM]; // [b][m][k] e4m3 (dequant value)
__device__ __align__(16) uint8_t g_Bq[(size_t)BATCH * DIM * DIM]; // [b][n][k] e4m3 (dequant value)

// ---------------------------------------------------------------------------
// Helpers
// ---------------------------------------------------------------------------
DI uint32_t smem_u32(const void* p) {
    uint32_t a;
    asm("{ .reg .u64 t; cvta.to.shared.u64 t, %1; cvt.u32.u64 %0, t; }" : "=r"(a) : "l"(p));
    return a;
}

DI void cp_async16(uint32_t dst, const void* src) {
    asm volatile("cp.async.cg.shared.global [%0], [%1], 16;" :: "r"(dst), "l"(src) : "memory");
}
DI void cp_commit() { asm volatile("cp.async.commit_group;" ::: "memory"); }
template <int N> DI void cp_wait() { asm volatile("cp.async.wait_group %0;" :: "n"(N) : "memory"); }

DI void ldmatrix_x4(uint32_t& r0, uint32_t& r1, uint32_t& r2, uint32_t& r3, uint32_t addr) {
    asm volatile("ldmatrix.sync.aligned.m8n8.x4.shared.b16 {%0,%1,%2,%3}, [%4];"
                 : "=r"(r0), "=r"(r1), "=r"(r2), "=r"(r3) : "r"(addr));
}

// FP8 e4m3 MMA, fp32 accumulate. Byte-level fragment layout identical to
// m16n8k16.bf16 (a2/b1 live at +16 bytes along k; 4-byte lane groups).
DI void mma_fp8(float& c0, float& c1, float& c2, float& c3,
                uint32_t a0, uint32_t a1, uint32_t a2, uint32_t a3,
                uint32_t b0, uint32_t b1) {
    asm volatile(
        "mma.sync.aligned.m16n8k32.row.col.f32.e4m3.e4m3.f32 "
        "{%0,%1,%2,%3}, {%4,%5,%6,%7}, {%8,%9}, {%0,%1,%2,%3};"
        : "+f"(c0), "+f"(c1), "+f"(c2), "+f"(c3)
        : "r"(a0), "r"(a1), "r"(a2), "r"(a3), "r"(b0), "r"(b1));
}

DI uint32_t swz(uint32_t off) { return off ^ ((off >> 3) & 0x70); }   // SW128, 128B rows

// ---------------------------------------------------------------------------
// MX fake-quantization -> e4m3 byte holding the exact dequantized value
// q * 2^(shexp-2), q in {0,.5,1,1.5,2,3,4,6}: mantissa <=1 bit -> e4m3-exact.
// ---------------------------------------------------------------------------
DI uint32_t quant_e4m3_val(float x, float inv, float scale) {
    float v = x * inv;                        // exact (power-of-2 inv)
    float a = fminf(fabsf(v), 6.0f);
    float q;
    if (a < 2.0f)      q = rintf(a * 2.0f) * 0.5f;   // step .5, RNE (== jnp.round)
    else if (a < 4.0f) q = rintf(a);                 // step 1
    else               q = rintf(a * 0.5f) * 2.0f;   // step 2
    float f = q * scale;                      // exact; e4m3-normal for all real data
    uint32_t b = 0;
    if (f != 0.0f)
        b = ((__float_as_uint(f) >> 20) - 960u) & 0x7Fu;   // fp32 -> e4m3 bits (exact)
    if (v < 0.0f) b |= 0x80u;
    return b;
}

DI void quant_block32(const float* x, uint32_t* w /*8 packed words*/) {
    float amax = 0.0f;
#pragma unroll
    for (int i = 0; i < 32; ++i) amax = fmaxf(amax, fabsf(x[i]));
    float inv, scale;
    if (amax > 0.0f) {
        int eb = (int)(__float_as_uint(amax) >> 23) & 0xFF;  // floor(log2)+127
        int sb = eb - 2;
        if (sb < 1) sb = 1;
        scale = __uint_as_float((uint32_t)sb << 23);          // exact 2^(shexp-2)
        inv   = __uint_as_float((uint32_t)(254 - sb) << 23);  // exact reciprocal
    } else {
        scale = 1.0f; inv = 1.0f;
    }
#pragma unroll
    for (int i = 0; i < 8; ++i) {
        uint32_t b0 = quant_e4m3_val(x[i*4+0], inv, scale);
        uint32_t b1 = quant_e4m3_val(x[i*4+1], inv, scale);
        uint32_t b2 = quant_e4m3_val(x[i*4+2], inv, scale);
        uint32_t b3 = quant_e4m3_val(x[i*4+3], inv, scale);
        w[i] = b0 | (b1 << 8) | (b2 << 16) | (b3 << 24);
    }
}

// A: [b][m][k] fp32, quantize along k (contiguous). One thread per 32-block.
__global__ void __launch_bounds__(256) quantA_kernel(const float* __restrict__ A) {
    size_t idx = (size_t)blockIdx.x * 256 + threadIdx.x;
    const float4* src = (const float4*)(A + idx * 32);
    float x[32];
#pragma unroll
    for (int i = 0; i < 8; ++i) {
        float4 v = src[i];
        x[i*4+0] = v.x; x[i*4+1] = v.y; x[i*4+2] = v.z; x[i*4+3] = v.w;
    }
    uint32_t w[8];
    quant_block32(x, w);
    uint4* dst = (uint4*)(g_Aq + idx * 32);
    dst[0] = make_uint4(w[0], w[1], w[2], w[3]);
    dst[1] = make_uint4(w[4], w[5], w[6], w[7]);
}

// B: [b][k][n] fp32, quantize along k (stride DIM). Output transposed: [b][n][k].
__global__ void __launch_bounds__(256) quantB_kernel(const float* __restrict__ B) {
    int n  = blockIdx.x * 256 + threadIdx.x;
    int kb = blockIdx.y;
    int b  = blockIdx.z;
    const float* src = B + ((size_t)b << 24) + (size_t)kb * 32 * DIM + n;
    float x[32];
#pragma unroll
    for (int r = 0; r < 32; ++r) x[r] = src[(size_t)r * DIM];
    uint32_t w[8];
    quant_block32(x, w);
    uint4* dst = (uint4*)(g_Bq + ((size_t)b << 24) + (size_t)n * DIM + kb * 32);
    dst[0] = make_uint4(w[0], w[1], w[2], w[3]);
    dst[1] = make_uint4(w[4], w[5], w[6], w[7]);
}

// ---------------------------------------------------------------------------
// GEMM: 128x256 CTA tile, e4m3 mma.sync m16n8k32, 3-stage cp.async pipeline
// 16 warps in 4x4 grid; warp tile 32(M) x 64(N); BK = 128 bytes per stage row.
// ---------------------------------------------------------------------------
DI void load_stage(uint32_t sb_, int stage, const uint8_t* Ab,
                   const uint8_t* Bb, int kt, int tid) {
    uint32_t sA = sb_ + stage * STAGE_B;
    uint32_t sB = sA + A_STAGE;
    const uint8_t* Ag = Ab + (size_t)kt * BK;
    const uint8_t* Bg = Bb + (size_t)kt * BK;
    // A: 128 rows x 128B = 1024 16B-chunks
#pragma unroll
    for (int t = 0; t < 2; ++t) {
        int c   = tid + t * NTHREADS;
        int row = c >> 3;
        int cc  = (c & 7) * 16;
        cp_async16(sA + swz((uint32_t)(row * 128 + cc)),
                   Ag + (size_t)row * DIM + cc);
    }
    // B: 256 rows x 128B = 2048 16B-chunks
#pragma unroll
    for (int t = 0; t < 4; ++t) {
        int c   = tid + t * NTHREADS;
        int row = c >> 3;
        int cc  = (c & 7) * 16;
        cp_async16(sB + swz((uint32_t)(row * 128 + cc)),
                   Bg + (size_t)row * DIM + cc);
    }
}

__global__ void __launch_bounds__(NTHREADS, 1)
gemm_kernel(float* __restrict__ out) {
    extern __shared__ char smem[];
    uint32_t sb_ = smem_u32(smem);
    int tid = threadIdx.x, warp = tid >> 5, lane = tid & 31;
    int wm = warp >> 2, wn = warp & 3;        // 4x4 warp grid
    int tn = blockIdx.x, tm = blockIdx.y, b = blockIdx.z;

    const uint8_t* Abase = g_Aq + ((size_t)b << 24) + (size_t)tm * BM * DIM;
    const uint8_t* Bbase = g_Bq + ((size_t)b << 24) + (size_t)tn * BN * DIM;

    float c[2][8][4];
#pragma unroll
    for (int i = 0; i < 2; ++i)
#pragma unroll
        for (int j = 0; j < 8; ++j)
#pragma unroll
            for (int q = 0; q < 4; ++q) c[i][j][q] = 0.0f;

    // prologue: prefetch STAGES-1 stages
#pragma unroll
    for (int p = 0; p < STAGES - 1; ++p) {
        load_stage(sb_, p, Abase, Bbase, p, tid);
        cp_commit();
    }

    // Pre-swizzled ldmatrix base addresses (ks=0). k-step advance is XOR:
    // base col-byte is 0/16 (bit 4), kx in {0,32,64,96} (bits 5-6), and the
    // swizzle XOR term depends only on row bits -> swz(base+kx)=swz(base)^kx.
    uint32_t a_base[2], b_base[4];
#pragma unroll
    for (int mt = 0; mt < 2; ++mt) {
        int r = wm * 32 + mt * 16 + (lane & 15);
        int cbyte = (lane >> 4) * 16;
        a_base[mt] = swz((uint32_t)(r * 128 + cbyte));
    }
#pragma unroll
    for (int p = 0; p < 4; ++p) {
        int m = lane >> 3;
        int r = wn * 64 + p * 16 + ((m >> 1) * 8) + (lane & 7);
        int cbyte = (m & 1) * 16;
        b_base[p] = swz((uint32_t)(r * 128 + cbyte));
    }

    for (int i = 0; i < KTILES; ++i) {
        cp_wait<STAGES - 2>();
        __syncthreads();          // single barrier per iteration

        int pf = i + STAGES - 1;
        if (pf < KTILES) {
            load_stage(sb_, pf % STAGES, Abase, Bbase, pf, tid);
        }
        cp_commit();              // uniform group count even when empty

        uint32_t stA = sb_ + (i % STAGES) * STAGE_B;
        uint32_t stB = stA + A_STAGE;
#pragma unroll
        for (int ks = 0; ks < 4; ++ks) {       // 4 x k32 = BK 128
            uint32_t kx = (uint32_t)(ks * 32);
            uint32_t af[2][4];
#pragma unroll
            for (int mt = 0; mt < 2; ++mt)
                ldmatrix_x4(af[mt][0], af[mt][1], af[mt][2], af[mt][3],
                            stA + (a_base[mt] ^ kx));
            uint32_t bf[8][2];
#pragma unroll
            for (int p = 0; p < 4; ++p) {
                uint32_t r0, r1, r2, r3;
                ldmatrix_x4(r0, r1, r2, r3, stB + (b_base[p] ^ kx));
                bf[p*2+0][0] = r0; bf[p*2+0][1] = r1;
                bf[p*2+1][0] = r2; bf[p*2+1][1] = r3;
            }
#pragma unroll
            for (int mt = 0; mt < 2; ++mt)
#pragma unroll
                for (int nt = 0; nt < 8; ++nt)
                    mma_fp8(c[mt][nt][0], c[mt][nt][1], c[mt][nt][2], c[mt][nt][3],
                            af[mt][0], af[mt][1], af[mt][2], af[mt][3],
                            bf[nt][0], bf[nt][1]);
        }
    }

    // epilogue: direct global stores (float2 per reg pair)
    int g = lane >> 2, t4 = lane & 3;
    float* obase = out + ((size_t)b << 24)
                 + (size_t)(tm * BM + wm * 32) * DIM + tn * BN + wn * 64;
#pragma unroll
    for (int mt = 0; mt < 2; ++mt) {
#pragma unroll
        for (int nt = 0; nt < 8; ++nt) {
            int colb = nt * 8 + t4 * 2;
            float* p0 = obase + (size_t)(mt * 16 + g) * DIM + colb;
            *(float2*)p0 = make_float2(c[mt][nt][0], c[mt][nt][1]);
            float* p1 = obase + (size_t)(mt * 16 + g + 8) * DIM + colb;
            *(float2*)p1 = make_float2(c[mt][nt][2], c[mt][nt][3]);
        }
    }
}

// ---------------------------------------------------------------------------
extern "C" void kernel_launch(void* const* d_in, const int* in_sizes, int n_in,
                              void* d_out, int out_size) {
    const float* A = (const float*)d_in[0];
    const float* B = (const float*)d_in[1];
    float* out = (float*)d_out;

    quantA_kernel<<<(BATCH * DIM * KB) / 256, 256>>>(A);
    quantB_kernel<<<dim3(DIM / 256, KB, BATCH), 256>>>(B);

    cudaFuncSetAttribute(gemm_kernel, cudaFuncAttributeMaxDynamicSharedMemorySize, SMEM_TOTAL);
    gemm_kernel<<<dim3(DIM / BN, DIM / BM, BATCH), NTHREADS, SMEM_TOTAL>>>(out);
}

// round 17
// speedup vs baseline: 1.0008x; 1.0003x over previous
#include <cuda_runtime.h>
#include <cuda_bf16.h>
#include <cstdint>
#include <cstddef>

#define DI __device__ __forceinline__

// ---------------------------------------------------------------------------
// Problem constants
// ---------------------------------------------------------------------------
static constexpr int BATCH = 4;
static constexpr int DIM   = 4096;
static constexpr int KB    = 128;            // 4096/32 scale blocks per vector

// GEMM tiling (element == byte for e4m3)
static constexpr int BM = 128, BN = 256, BK = 128;   // BK in elements (=bytes)
static constexpr int NTHREADS = 512;          // 16 warps, 4x4
static constexpr int STAGES  = 3;
static constexpr int KTILES  = DIM / BK;      // 32
static constexpr int A_STAGE = BM * BK;       // 16384 B
static constexpr int B_STAGE = BN * BK;       // 32768 B
static constexpr int STAGE_B = A_STAGE + B_STAGE;            // 49152
static constexpr unsigned SMEM_TOTAL = STAGES * STAGE_B;     // 147456

// ---------------------------------------------------------------------------
// Scratch (device globals; no cudaMalloc allowed)
// ---------------------------------------------------------------------------
__device__ __align__(16) uint8_t g_Aq[(size_t)BATCH * DIM * DIM]; // [b][m][k] e4m3 (dequant value)
__device__ __align__(16) uint8_t g_Bq[(size_t)BATCH * DIM * DIM]; // [b][n][k] e4m3 (dequant value)

// ---------------------------------------------------------------------------
// Helpers
// ---------------------------------------------------------------------------
DI uint32_t smem_u32(const void* p) {
    uint32_t a;
    asm("{ .reg .u64 t; cvta.to.shared.u64 t, %1; cvt.u32.u64 %0, t; }" : "=r"(a) : "l"(p));
    return a;
}

DI void cp_async16(uint32_t dst, const void* src) {
    asm volatile("cp.async.cg.shared.global [%0], [%1], 16;" :: "r"(dst), "l"(src) : "memory");
}
DI void cp_commit() { asm volatile("cp.async.commit_group;" ::: "memory"); }
template <int N> DI void cp_wait() { asm volatile("cp.async.wait_group %0;" :: "n"(N) : "memory"); }

DI void ldmatrix_x4(uint32_t& r0, uint32_t& r1, uint32_t& r2, uint32_t& r3, uint32_t addr) {
    asm volatile("ldmatrix.sync.aligned.m8n8.x4.shared.b16 {%0,%1,%2,%3}, [%4];"
                 : "=r"(r0), "=r"(r1), "=r"(r2), "=r"(r3) : "r"(addr));
}

// FP8 e4m3 MMA, fp32 accumulate. Byte-level fragment layout identical to
// m16n8k16.bf16 (a2/b1 live at +16 bytes along k; 4-byte lane groups).
DI void mma_fp8(float& c0, float& c1, float& c2, float& c3,
                uint32_t a0, uint32_t a1, uint32_t a2, uint32_t a3,
                uint32_t b0, uint32_t b1) {
    asm volatile(
        "mma.sync.aligned.m16n8k32.row.col.f32.e4m3.e4m3.f32 "
        "{%0,%1,%2,%3}, {%4,%5,%6,%7}, {%8,%9}, {%0,%1,%2,%3};"
        : "+f"(c0), "+f"(c1), "+f"(c2), "+f"(c3)
        : "r"(a0), "r"(a1), "r"(a2), "r"(a3), "r"(b0), "r"(b1));
}

DI uint32_t swz(uint32_t off) { return off ^ ((off >> 3) & 0x70); }   // SW128, 128B rows

// ---------------------------------------------------------------------------
// MX fake-quantization -> e4m3 byte holding the exact dequantized value
// q * 2^(shexp-2), q in {0,.5,1,1.5,2,3,4,6}: mantissa <=1 bit -> e4m3-exact.
// ---------------------------------------------------------------------------
DI uint32_t quant_e4m3_val(float x, float inv, float scale) {
    float v = x * inv;                        // exact (power-of-2 inv)
    float a = fminf(fabsf(v), 6.0f);
    float q;
    if (a < 2.0f)      q = rintf(a * 2.0f) * 0.5f;   // step .5, RNE (== jnp.round)
    else if (a < 4.0f) q = rintf(a);                 // step 1
    else               q = rintf(a * 0.5f) * 2.0f;   // step 2
    float f = q * scale;                      // exact; e4m3-normal for all real data
    uint32_t b = 0;
    if (f != 0.0f)
        b = ((__float_as_uint(f) >> 20) - 960u) & 0x7Fu;   // fp32 -> e4m3 bits (exact)
    if (v < 0.0f) b |= 0x80u;
    return b;
}

DI void quant_block32(const float* x, uint32_t* w /*8 packed words*/) {
    float amax = 0.0f;
#pragma unroll
    for (int i = 0; i < 32; ++i) amax = fmaxf(amax, fabsf(x[i]));
    float inv, scale;
    if (amax > 0.0f) {
        int eb = (int)(__float_as_uint(amax) >> 23) & 0xFF;  // floor(log2)+127
        int sb = eb - 2;
        if (sb < 1) sb = 1;
        scale = __uint_as_float((uint32_t)sb << 23);          // exact 2^(shexp-2)
        inv   = __uint_as_float((uint32_t)(254 - sb) << 23);  // exact reciprocal
    } else {
        scale = 1.0f; inv = 1.0f;
    }
#pragma unroll
    for (int i = 0; i < 8; ++i) {
        uint32_t b0 = quant_e4m3_val(x[i*4+0], inv, scale);
        uint32_t b1 = quant_e4m3_val(x[i*4+1], inv, scale);
        uint32_t b2 = quant_e4m3_val(x[i*4+2], inv, scale);
        uint32_t b3 = quant_e4m3_val(x[i*4+3], inv, scale);
        w[i] = b0 | (b1 << 8) | (b2 << 16) | (b3 << 24);
    }
}

// A: [b][m][k] fp32, quantize along k (contiguous). One thread per 32-block.
__global__ void __launch_bounds__(256) quantA_kernel(const float* __restrict__ A) {
    size_t idx = (size_t)blockIdx.x * 256 + threadIdx.x;
    const float4* src = (const float4*)(A + idx * 32);
    float x[32];
#pragma unroll
    for (int i = 0; i < 8; ++i) {
        float4 v = src[i];
        x[i*4+0] = v.x; x[i*4+1] = v.y; x[i*4+2] = v.z; x[i*4+3] = v.w;
    }
    uint32_t w[8];
    quant_block32(x, w);
    uint4* dst = (uint4*)(g_Aq + idx * 32);
    dst[0] = make_uint4(w[0], w[1], w[2], w[3]);
    dst[1] = make_uint4(w[4], w[5], w[6], w[7]);
}

// B: [b][k][n] fp32, quantize along k (stride DIM). Output transposed: [b][n][k].
__global__ void __launch_bounds__(256) quantB_kernel(const float* __restrict__ B) {
    int n  = blockIdx.x * 256 + threadIdx.x;
    int kb = blockIdx.y;
    int b  = blockIdx.z;
    const float* src = B + ((size_t)b << 24) + (size_t)kb * 32 * DIM + n;
    float x[32];
#pragma unroll
    for (int r = 0; r < 32; ++r) x[r] = src[(size_t)r * DIM];
    uint32_t w[8];
    quant_block32(x, w);
    uint4* dst = (uint4*)(g_Bq + ((size_t)b << 24) + (size_t)n * DIM + kb * 32);
    dst[0] = make_uint4(w[0], w[1], w[2], w[3]);
    dst[1] = make_uint4(w[4], w[5], w[6], w[7]);
}

// ---------------------------------------------------------------------------
// GEMM: 128x256 CTA tile, e4m3 mma.sync m16n8k32, 3-stage cp.async pipeline
// 16 warps in 4x4 grid; warp tile 32(M) x 64(N); BK = 128 bytes per stage row.
// ---------------------------------------------------------------------------
DI void load_stage(uint32_t sb_, int stage, const uint8_t* Ab,
                   const uint8_t* Bb, int kt, int tid) {
    uint32_t sA = sb_ + stage * STAGE_B;
    uint32_t sB = sA + A_STAGE;
    const uint8_t* Ag = Ab + (size_t)kt * BK;
    const uint8_t* Bg = Bb + (size_t)kt * BK;
    // A: 128 rows x 128B = 1024 16B-chunks
#pragma unroll
    for (int t = 0; t < 2; ++t) {
        int c   = tid + t * NTHREADS;
        int row = c >> 3;
        int cc  = (c & 7) * 16;
        cp_async16(sA + swz((uint32_t)(row * 128 + cc)),
                   Ag + (size_t)row * DIM + cc);
    }
    // B: 256 rows x 128B = 2048 16B-chunks
#pragma unroll
    for (int t = 0; t < 4; ++t) {
        int c   = tid + t * NTHREADS;
        int row = c >> 3;
        int cc  = (c & 7) * 16;
        cp_async16(sB + swz((uint32_t)(row * 128 + cc)),
                   Bg + (size_t)row * DIM + cc);
    }
}

__global__ void __launch_bounds__(NTHREADS, 1)
gemm_kernel(float* __restrict__ out) {
    extern __shared__ char smem[];
    uint32_t sb_ = smem_u32(smem);
    int tid = threadIdx.x, warp = tid >> 5, lane = tid & 31;
    int wm = warp >> 2, wn = warp & 3;        // 4x4 warp grid
    int tn = blockIdx.x, tm = blockIdx.y, b = blockIdx.z;

    const uint8_t* Abase = g_Aq + ((size_t)b << 24) + (size_t)tm * BM * DIM;
    const uint8_t* Bbase = g_Bq + ((size_t)b << 24) + (size_t)tn * BN * DIM;

    float c[2][8][4];
#pragma unroll
    for (int i = 0; i < 2; ++i)
#pragma unroll
        for (int j = 0; j < 8; ++j)
#pragma unroll
            for (int q = 0; q < 4; ++q) c[i][j][q] = 0.0f;

    // prologue: prefetch STAGES-1 stages
#pragma unroll
    for (int p = 0; p < STAGES - 1; ++p) {
        load_stage(sb_, p, Abase, Bbase, p, tid);
        cp_commit();
    }

    // Pre-swizzled ldmatrix base addresses (ks=0). k-step advance is XOR:
    // base col-byte is 0/16 (bit 4), kx in {0,32,64,96} (bits 5-6), and the
    // swizzle XOR term depends only on row bits -> swz(base+kx)=swz(base)^kx.
    uint32_t a_base[2], b_base[4];
#pragma unroll
    for (int mt = 0; mt < 2; ++mt) {
        int r = wm * 32 + mt * 16 + (lane & 15);
        int cbyte = (lane >> 4) * 16;
        a_base[mt] = swz((uint32_t)(r * 128 + cbyte));
    }
#pragma unroll
    for (int p = 0; p < 4; ++p) {
        int m = lane >> 3;
        int r = wn * 64 + p * 16 + ((m >> 1) * 8) + (lane & 7);
        int cbyte = (m & 1) * 16;
        b_base[p] = swz((uint32_t)(r * 128 + cbyte));
    }

    for (int i = 0; i < KTILES; ++i) {
        cp_wait<STAGES - 2>();
        __syncthreads();          // single barrier per iteration

        int pf = i + STAGES - 1;
        if (pf < KTILES) {
            load_stage(sb_, pf % STAGES, Abase, Bbase, pf, tid);
        }
        cp_commit();              // uniform group count even when empty

        uint32_t stA = sb_ + (i % STAGES) * STAGE_B;
        uint32_t stB = stA + A_STAGE;
#pragma unroll
        for (int ks = 0; ks < 4; ++ks) {       // 4 x k32 = BK 128
            uint32_t kx = (uint32_t)(ks * 32);
            uint32_t af[2][4];
#pragma unroll
            for (int mt = 0; mt < 2; ++mt)
                ldmatrix_x4(af[mt][0], af[mt][1], af[mt][2], af[mt][3],
                            stA + (a_base[mt] ^ kx));
            uint32_t bf[8][2];
#pragma unroll
            for (int p = 0; p < 4; ++p) {
                uint32_t r0, r1, r2, r3;
                ldmatrix_x4(r0, r1, r2, r3, stB + (b_base[p] ^ kx));
                bf[p*2+0][0] = r0; bf[p*2+0][1] = r1;
                bf[p*2+1][0] = r2; bf[p*2+1][1] = r3;
            }
#pragma unroll
            for (int mt = 0; mt < 2; ++mt)
#pragma unroll
                for (int nt = 0; nt < 8; ++nt)
                    mma_fp8(c[mt][nt][0], c[mt][nt][1], c[mt][nt][2], c[mt][nt][3],
                            af[mt][0], af[mt][1], af[mt][2], af[mt][3],
                            bf[nt][0], bf[nt][1]);
        }
    }

    // epilogue: direct global stores (float2 per reg pair)
    int g = lane >> 2, t4 = lane & 3;
    float* obase = out + ((size_t)b << 24)
                 + (size_t)(tm * BM + wm * 32) * DIM + tn * BN + wn * 64;
#pragma unroll
    for (int mt = 0; mt < 2; ++mt) {
#pragma unroll
        for (int nt = 0; nt < 8; ++nt) {
            int colb = nt * 8 + t4 * 2;
            float* p0 = obase + (size_t)(mt * 16 + g) * DIM + colb;
            *(float2*)p0 = make_float2(c[mt][nt][0], c[mt][nt][1]);
            float* p1 = obase + (size_t)(mt * 16 + g + 8) * DIM + colb;
            *(float2*)p1 = make_float2(c[mt][nt][2], c[mt][nt][3]);
        }
    }
}

// ---------------------------------------------------------------------------
extern "C" void kernel_launch(void* const* d_in, const int* in_sizes, int n_in,
                              void* d_out, int out_size) {
    const float* A = (const float*)d_in[0];
    const float* B = (const float*)d_in[1];
    float* out = (float*)d_out;

    quantA_kernel<<<(BATCH * DIM * KB) / 256, 256>>>(A);
    quantB_kernel<<<dim3(DIM / 256, KB, BATCH), 256>>>(B);

    cudaFuncSetAttribute(gemm_kernel, cudaFuncAttributeMaxDynamicSharedMemorySize, SMEM_TOTAL);
    gemm_kernel<<<dim3(DIM / BN, DIM / BM, BATCH), NTHREADS, SMEM_TOTAL>>>(out);
}